// round 4
// baseline (speedup 1.0000x reference)
#include <cuda_runtime.h>
#include <math.h>

#define F      128
#define HEADS  4
#define NMAX   50000
#define GMAX   64
#define EMAX   860000
#define XPAD   68

// ---------------- device scratch ----------------
__device__ __align__(16) float g_h   [NMAX * F];
__device__ __align__(16) float g_buf [NMAX * F];
__device__ __align__(16) float g_as  [NMAX * HEADS];
__device__ __align__(16) float g_ad  [NMAX * HEADS];
__device__ __align__(16) float g_psum[GMAX * F];
__device__ __align__(16) float g_pmax[GMAX * F];
__device__             float g_cnt [GMAX];
__device__             int   g_deg [NMAX];
__device__             int   g_rowptr[NMAX + 1];
__device__             int   g_wpos[NMAX];
__device__             int   g_csrc[EMAX];

// ---------------- helpers ----------------
__device__ __forceinline__ void atomicMaxFloat(float* addr, float value) {
    if (value >= 0.f) atomicMax((int*)addr, __float_as_int(value));
    else              atomicMin((unsigned int*)addr, __float_as_uint(value));
}

__device__ __forceinline__ void redAddV4(float* p, float a, float b, float c, float d) {
    asm volatile("red.global.add.v4.f32 [%0], {%1,%2,%3,%4};"
                 :: "l"(p), "f"(a), "f"(b), "f"(c), "f"(d) : "memory");
}

// ---------------- GEMM + fused alpha: O = X @ W; g_as/g_ad per node ----------------
__global__ void gemm_k(const float* __restrict__ X, const float* __restrict__ W,
                       float* __restrict__ O,
                       const float* __restrict__ asr, const float* __restrict__ adt,
                       int N) {
    extern __shared__ float sm[];
    float* ws = sm;            // [128][128]
    float* xs = sm + F * F;    // [128][XPAD]

    const int tid  = threadIdx.x;
    const int row0 = blockIdx.x * 64;

    const float4* W4  = (const float4*)W;
    float4*       ws4 = (float4*)ws;
#pragma unroll
    for (int i = 0; i < 16; i++) ws4[tid + i * 256] = W4[tid + i * 256];

    const float4* X4 = (const float4*)X;
#pragma unroll
    for (int i = 0; i < 8; i++) {
        int idx = tid + i * 256;
        int r = idx >> 5, kq = idx & 31;
        float4 v = make_float4(0.f, 0.f, 0.f, 0.f);
        int gr = row0 + r;
        if (gr < N) v = X4[gr * 32 + kq];
        xs[(4 * kq + 0) * XPAD + r] = v.x;
        xs[(4 * kq + 1) * XPAD + r] = v.y;
        xs[(4 * kq + 2) * XPAD + r] = v.z;
        xs[(4 * kq + 3) * XPAD + r] = v.w;
    }
    __syncthreads();

    const int ty = tid >> 4, tx = tid & 15;
    float acc[4][8];
#pragma unroll
    for (int i = 0; i < 4; i++)
#pragma unroll
        for (int j = 0; j < 8; j++) acc[i][j] = 0.f;

#pragma unroll 4
    for (int k = 0; k < F; k++) {
        float4 x4 = *(const float4*)&xs[k * XPAD + ty * 4];
        float xr[4] = {x4.x, x4.y, x4.z, x4.w};
        float4 w0 = *(const float4*)&ws[k * F + tx * 8];
        float4 w1 = *(const float4*)&ws[k * F + tx * 8 + 4];
        float wr[8] = {w0.x, w0.y, w0.z, w0.w, w1.x, w1.y, w1.z, w1.w};
#pragma unroll
        for (int i = 0; i < 4; i++)
#pragma unroll
            for (int j = 0; j < 8; j++) acc[i][j] = fmaf(xr[i], wr[j], acc[i][j]);
    }

    // attention vectors for this thread's 8 columns (head = tx>>2)
    float4 a0 = *(const float4*)&asr[tx * 8];
    float4 a1 = *(const float4*)&asr[tx * 8 + 4];
    float4 d0 = *(const float4*)&adt[tx * 8];
    float4 d1 = *(const float4*)&adt[tx * 8 + 4];
    float av[8] = {a0.x, a0.y, a0.z, a0.w, a1.x, a1.y, a1.z, a1.w};
    float dv[8] = {d0.x, d0.y, d0.z, d0.w, d1.x, d1.y, d1.z, d1.w};

    const int lane = tid & 31;
    const int head = (lane >> 2) & 3;

#pragma unroll
    for (int i = 0; i < 4; i++) {
        int gr = row0 + ty * 4 + i;
        float ps = 0.f, pd = 0.f;
#pragma unroll
        for (int j = 0; j < 8; j++) {
            ps = fmaf(acc[i][j], av[j], ps);
            pd = fmaf(acc[i][j], dv[j], pd);
        }
        ps += __shfl_down_sync(0xffffffffu, ps, 1, 4);
        ps += __shfl_down_sync(0xffffffffu, ps, 2, 4);
        pd += __shfl_down_sync(0xffffffffu, pd, 1, 4);
        pd += __shfl_down_sync(0xffffffffu, pd, 2, 4);
        if (gr < N) {
            if ((lane & 3) == 0) {
                g_as[gr * 4 + head] = ps;
                g_ad[gr * 4 + head] = pd;
            }
            *(float4*)&O[gr * F + tx * 8]     = make_float4(acc[i][0], acc[i][1], acc[i][2], acc[i][3]);
            *(float4*)&O[gr * F + tx * 8 + 4] = make_float4(acc[i][4], acc[i][5], acc[i][6], acc[i][7]);
        }
    }
}

// ---------------- CSR build ----------------
__global__ void zero_deg_k(int N) {
    int i = blockIdx.x * blockDim.x + threadIdx.x;
    if (i < N) g_deg[i] = 0;
}

__global__ void count_k(const int* __restrict__ ei, int E, int N) {
    int i = blockIdx.x * blockDim.x + threadIdx.x;
    int Et = E + N;
    if (i >= Et) return;
    int dst = (i < E) ? ei[E + i] : (i - E);
    atomicAdd(&g_deg[dst], 1);
}

// single-block exclusive scan (warp-shuffle based)
__global__ void scan_k(int N) {
    __shared__ int warpsum[32];
    __shared__ int carry_s;
    int tid = threadIdx.x, lane = tid & 31, wid = tid >> 5;
    if (tid == 0) carry_s = 0;
    __syncthreads();
    for (int base = 0; base < N; base += 1024) {
        int i = base + tid;
        int v = (i < N) ? g_deg[i] : 0;
        int x = v;
#pragma unroll
        for (int o = 1; o < 32; o <<= 1) {
            int t = __shfl_up_sync(0xffffffffu, x, o);
            if (lane >= o) x += t;
        }
        if (lane == 31) warpsum[wid] = x;
        __syncthreads();
        if (wid == 0) {
            int s = warpsum[lane];
#pragma unroll
            for (int o = 1; o < 32; o <<= 1) {
                int t = __shfl_up_sync(0xffffffffu, s, o);
                if (lane >= o) s += t;
            }
            warpsum[lane] = s;
        }
        __syncthreads();
        int pref  = (wid > 0) ? warpsum[wid - 1] : 0;
        int incl  = carry_s + pref + x;
        int excl  = incl - v;
        if (i < N) { g_rowptr[i] = excl; g_wpos[i] = excl; }
        __syncthreads();
        if (tid == 1023) carry_s = incl;
        __syncthreads();
    }
    if (threadIdx.x == 0) g_rowptr[N] = carry_s;
}

__global__ void scatter_k(const int* __restrict__ ei, int E, int N) {
    int i = blockIdx.x * blockDim.x + threadIdx.x;
    int Et = E + N;
    if (i >= Et) return;
    int src, dst;
    if (i < E) { src = ei[i]; dst = ei[E + i]; }
    else       { src = dst = i - E; }
    int pos = atomicAdd(&g_wpos[dst], 1);
    g_csrc[pos] = src;
}

// ---------------- fused softmax + aggregation + bias (+ELU / +pool), warp per dst ----------------
__global__ void aggr_k(const float* __restrict__ Hm,
                       float* __restrict__ O,
                       const float* __restrict__ bias,
                       const int* __restrict__ batch,
                       int N, int do_elu, int do_pool) {
    int d    = (blockIdx.x * blockDim.x + threadIdx.x) >> 5;
    int lane = threadIdx.x & 31;
    if (d >= N) return;
    int head = lane >> 3;

    float adh = g_ad[d * 4 + head];
    int i0 = g_rowptr[d];
    int i1 = g_rowptr[d + 1];

    float4 acc0 = make_float4(0.f, 0.f, 0.f, 0.f);
    float4 acc1 = make_float4(0.f, 0.f, 0.f, 0.f);
    float sw0 = 0.f, sw1 = 0.f;

    int i = i0;
    for (; i + 1 < i1; i += 2) {
        int s0 = __ldg(&g_csrc[i]);
        int s1 = __ldg(&g_csrc[i + 1]);
        float a0 = __ldg(&g_as[s0 * 4 + head]);
        float a1 = __ldg(&g_as[s1 * 4 + head]);
        float4 h0 = *(const float4*)&Hm[s0 * F + lane * 4];
        float4 h1 = *(const float4*)&Hm[s1 * F + lane * 4];
        float e0 = a0 + adh; e0 = e0 > 0.f ? e0 : 0.2f * e0;
        float e1 = a1 + adh; e1 = e1 > 0.f ? e1 : 0.2f * e1;
        float w0 = __expf(e0);
        float w1 = __expf(e1);
        sw0 += w0;             sw1 += w1;
        acc0.x = fmaf(w0, h0.x, acc0.x);  acc1.x = fmaf(w1, h1.x, acc1.x);
        acc0.y = fmaf(w0, h0.y, acc0.y);  acc1.y = fmaf(w1, h1.y, acc1.y);
        acc0.z = fmaf(w0, h0.z, acc0.z);  acc1.z = fmaf(w1, h1.z, acc1.z);
        acc0.w = fmaf(w0, h0.w, acc0.w);  acc1.w = fmaf(w1, h1.w, acc1.w);
    }
    if (i < i1) {
        int s0 = __ldg(&g_csrc[i]);
        float a0 = __ldg(&g_as[s0 * 4 + head]);
        float4 h0 = *(const float4*)&Hm[s0 * F + lane * 4];
        float e0 = a0 + adh; e0 = e0 > 0.f ? e0 : 0.2f * e0;
        float w0 = __expf(e0);
        sw0 += w0;
        acc0.x = fmaf(w0, h0.x, acc0.x);
        acc0.y = fmaf(w0, h0.y, acc0.y);
        acc0.z = fmaf(w0, h0.z, acc0.z);
        acc0.w = fmaf(w0, h0.w, acc0.w);
    }

    float sw = sw0 + sw1;
    float inv = 1.0f / (sw + 1e-16f);
    float4 b4 = *(const float4*)&bias[lane * 4];
    float4 o;
    o.x = (acc0.x + acc1.x) * inv + b4.x;
    o.y = (acc0.y + acc1.y) * inv + b4.y;
    o.z = (acc0.z + acc1.z) * inv + b4.z;
    o.w = (acc0.w + acc1.w) * inv + b4.w;
    if (do_elu) {
        o.x = o.x > 0.f ? o.x : expm1f(o.x);
        o.y = o.y > 0.f ? o.y : expm1f(o.y);
        o.z = o.z > 0.f ? o.z : expm1f(o.z);
        o.w = o.w > 0.f ? o.w : expm1f(o.w);
    }

    if (do_pool) {
        int g = __ldg(&batch[d]);
        redAddV4(&g_psum[g * F + lane * 4], o.x, o.y, o.z, o.w);
        atomicMaxFloat(&g_pmax[g * F + lane * 4 + 0], o.x);
        atomicMaxFloat(&g_pmax[g * F + lane * 4 + 1], o.y);
        atomicMaxFloat(&g_pmax[g * F + lane * 4 + 2], o.z);
        atomicMaxFloat(&g_pmax[g * F + lane * 4 + 3], o.w);
        if (lane == 0) atomicAdd(&g_cnt[g], 1.0f);
    } else {
        *(float4*)&O[d * F + lane * 4] = o;
    }
}

// ---------------- pooling init + final ----------------
__global__ void pool_init_k() {
    int i = blockIdx.x * blockDim.x + threadIdx.x;
    if (i < GMAX * F) { g_psum[i] = 0.f; g_pmax[i] = -INFINITY; }
    if (i < GMAX) g_cnt[i] = 0.f;
}

__global__ void final_k(const float* __restrict__ lw, const float* __restrict__ lb,
                        float* __restrict__ out) {
    int g    = (blockIdx.x * blockDim.x + threadIdx.x) >> 5;
    int lane = threadIdx.x & 31;
    if (g >= GMAX) return;
    float cnt = fmaxf(g_cnt[g], 1.0f);
    float acc = 0.f;
#pragma unroll
    for (int j = 0; j < 4; j++) {
        int c = lane * 4 + j;
        float mean = g_psum[g * F + c] / cnt;
        float mx = g_pmax[g * F + c];
        if (isinf(mx)) mx = 0.f;
        acc += (mean + mx) * lw[c];
    }
#pragma unroll
    for (int o = 16; o; o >>= 1) acc += __shfl_down_sync(0xffffffffu, acc, o);
    if (lane == 0) out[g] = acc + lb[0];
}

// ---------------- launcher ----------------
extern "C" void kernel_launch(void* const* d_in, const int* in_sizes, int n_in,
                              void* d_out, int out_size) {
    const float* x     = (const float*)d_in[0];
    const int*   ei    = (const int*)d_in[1];
    const int*   batch = (const int*)d_in[2];
    const float* W1    = (const float*)d_in[3];
    const float* as1   = (const float*)d_in[4];
    const float* ad1   = (const float*)d_in[5];
    const float* b1    = (const float*)d_in[6];
    const float* W2    = (const float*)d_in[7];
    const float* as2   = (const float*)d_in[8];
    const float* ad2   = (const float*)d_in[9];
    const float* b2    = (const float*)d_in[10];
    const float* lw    = (const float*)d_in[11];
    const float* lb    = (const float*)d_in[12];

    int N  = in_sizes[0] / F;
    int E  = in_sizes[1] / 2;
    int Et = E + N;

    float *hptr, *bptr;
    cudaGetSymbolAddress((void**)&hptr, g_h);
    cudaGetSymbolAddress((void**)&bptr, g_buf);

    size_t smem = (size_t)(F * F + F * XPAD) * sizeof(float);
    cudaFuncSetAttribute(gemm_k, cudaFuncAttributeMaxDynamicSharedMemorySize, (int)smem);

    int gemm_blocks      = (N + 63) / 64;
    int node_warp_blocks = (N * 32 + 255) / 256;
    int edge_blocks      = (Et + 255) / 256;

    // ---- CSR build (topology shared by both layers) ----
    zero_deg_k<<<(N + 255) / 256, 256>>>(N);
    count_k<<<edge_blocks, 256>>>(ei, E, N);
    scan_k<<<1, 1024>>>(N);
    scatter_k<<<edge_blocks, 256>>>(ei, E, N);

    // ---- layer 1 (gemm + fused alpha, then fused softmax-aggregate+bias+ELU) ----
    gemm_k<<<gemm_blocks, 256, smem>>>(x, W1, hptr, as1, ad1, N);
    aggr_k<<<node_warp_blocks, 256>>>(hptr, bptr, b1, batch, N, 1, 0);

    // ---- layer 2 (pool fused into aggregation epilogue) ----
    pool_init_k<<<(GMAX * F + 255) / 256, 256>>>();
    gemm_k<<<gemm_blocks, 256, smem>>>(bptr, W2, hptr, as2, ad2, N);
    aggr_k<<<node_warp_blocks, 256>>>(hptr, bptr, b2, batch, N, 0, 1);

    // ---- final linear ----
    final_k<<<(GMAX * 32 + 255) / 256, 256>>>(lw, lb, (float*)d_out);
}

// round 5
// speedup vs baseline: 1.1629x; 1.1629x over previous
#include <cuda_runtime.h>
#include <math.h>

#define F      128
#define HEADS  4
#define NMAX   50000
#define GMAX   64
#define EMAX   860000
#define XPAD   68

// ---------------- device scratch ----------------
__device__ __align__(16) float g_h   [NMAX * F];
__device__ __align__(16) float g_buf [NMAX * F];
__device__ __align__(16) float g_as  [NMAX * HEADS];
__device__ __align__(16) float g_ad  [NMAX * HEADS];
__device__ __align__(16) float g_psum[GMAX * F];
__device__ __align__(16) float g_pmax[GMAX * F];
__device__             float g_cnt [GMAX];
__device__             int   g_deg [NMAX];
__device__             int   g_rowptr[NMAX + 1];
__device__             int   g_wpos[NMAX];
__device__             int   g_csrc[EMAX];

// ---------------- helpers ----------------
__device__ __forceinline__ void atomicMaxFloat(float* addr, float value) {
    if (value >= 0.f) atomicMax((int*)addr, __float_as_int(value));
    else              atomicMin((unsigned int*)addr, __float_as_uint(value));
}

__device__ __forceinline__ void redAddV4(float* p, float a, float b, float c, float d) {
    asm volatile("red.global.add.v4.f32 [%0], {%1,%2,%3,%4};"
                 :: "l"(p), "f"(a), "f"(b), "f"(c), "f"(d) : "memory");
}

// ---------------- GEMM + fused alpha: O = X @ W; g_as/g_ad per node ----------------
__global__ void gemm_k(const float* __restrict__ X, const float* __restrict__ W,
                       float* __restrict__ O,
                       const float* __restrict__ asr, const float* __restrict__ adt,
                       int N) {
    extern __shared__ float sm[];
    float* ws = sm;            // [128][128]
    float* xs = sm + F * F;    // [128][XPAD]

    const int tid  = threadIdx.x;
    const int row0 = blockIdx.x * 64;

    const float4* W4  = (const float4*)W;
    float4*       ws4 = (float4*)ws;
#pragma unroll
    for (int i = 0; i < 16; i++) ws4[tid + i * 256] = W4[tid + i * 256];

    const float4* X4 = (const float4*)X;
#pragma unroll
    for (int i = 0; i < 8; i++) {
        int idx = tid + i * 256;
        int r = idx >> 5, kq = idx & 31;
        float4 v = make_float4(0.f, 0.f, 0.f, 0.f);
        int gr = row0 + r;
        if (gr < N) v = X4[gr * 32 + kq];
        xs[(4 * kq + 0) * XPAD + r] = v.x;
        xs[(4 * kq + 1) * XPAD + r] = v.y;
        xs[(4 * kq + 2) * XPAD + r] = v.z;
        xs[(4 * kq + 3) * XPAD + r] = v.w;
    }
    __syncthreads();

    const int ty = tid >> 4, tx = tid & 15;
    float acc[4][8];
#pragma unroll
    for (int i = 0; i < 4; i++)
#pragma unroll
        for (int j = 0; j < 8; j++) acc[i][j] = 0.f;

#pragma unroll 4
    for (int k = 0; k < F; k++) {
        float4 x4 = *(const float4*)&xs[k * XPAD + ty * 4];
        float xr[4] = {x4.x, x4.y, x4.z, x4.w};
        float4 w0 = *(const float4*)&ws[k * F + tx * 8];
        float4 w1 = *(const float4*)&ws[k * F + tx * 8 + 4];
        float wr[8] = {w0.x, w0.y, w0.z, w0.w, w1.x, w1.y, w1.z, w1.w};
#pragma unroll
        for (int i = 0; i < 4; i++)
#pragma unroll
            for (int j = 0; j < 8; j++) acc[i][j] = fmaf(xr[i], wr[j], acc[i][j]);
    }

    // attention vectors for this thread's 8 columns (head = tx>>2)
    float4 a0 = *(const float4*)&asr[tx * 8];
    float4 a1 = *(const float4*)&asr[tx * 8 + 4];
    float4 d0 = *(const float4*)&adt[tx * 8];
    float4 d1 = *(const float4*)&adt[tx * 8 + 4];
    float av[8] = {a0.x, a0.y, a0.z, a0.w, a1.x, a1.y, a1.z, a1.w};
    float dv[8] = {d0.x, d0.y, d0.z, d0.w, d1.x, d1.y, d1.z, d1.w};

    const int lane = tid & 31;
    const int head = (lane >> 2) & 3;

#pragma unroll
    for (int i = 0; i < 4; i++) {
        int gr = row0 + ty * 4 + i;
        float ps = 0.f, pd = 0.f;
#pragma unroll
        for (int j = 0; j < 8; j++) {
            ps = fmaf(acc[i][j], av[j], ps);
            pd = fmaf(acc[i][j], dv[j], pd);
        }
        ps += __shfl_down_sync(0xffffffffu, ps, 1, 4);
        ps += __shfl_down_sync(0xffffffffu, ps, 2, 4);
        pd += __shfl_down_sync(0xffffffffu, pd, 1, 4);
        pd += __shfl_down_sync(0xffffffffu, pd, 2, 4);
        if (gr < N) {
            if ((lane & 3) == 0) {
                g_as[gr * 4 + head] = ps;
                g_ad[gr * 4 + head] = pd;
            }
            *(float4*)&O[gr * F + tx * 8]     = make_float4(acc[i][0], acc[i][1], acc[i][2], acc[i][3]);
            *(float4*)&O[gr * F + tx * 8 + 4] = make_float4(acc[i][4], acc[i][5], acc[i][6], acc[i][7]);
        }
    }
}

// ---------------- CSR build ----------------
__global__ void zero_deg_k(int N) {
    int i = blockIdx.x * blockDim.x + threadIdx.x;
    if (i < N) g_deg[i] = 0;
}

__global__ void count_k(const int* __restrict__ ei, int E, int N) {
    int i = blockIdx.x * blockDim.x + threadIdx.x;
    int Et = E + N;
    if (i >= Et) return;
    int dst = (i < E) ? ei[E + i] : (i - E);
    atomicAdd(&g_deg[dst], 1);
}

// single-block exclusive scan (warp-shuffle based)
__global__ void scan_k(int N) {
    __shared__ int warpsum[32];
    __shared__ int carry_s;
    int tid = threadIdx.x, lane = tid & 31, wid = tid >> 5;
    if (tid == 0) carry_s = 0;
    __syncthreads();
    for (int base = 0; base < N; base += 1024) {
        int i = base + tid;
        int v = (i < N) ? g_deg[i] : 0;
        int x = v;
#pragma unroll
        for (int o = 1; o < 32; o <<= 1) {
            int t = __shfl_up_sync(0xffffffffu, x, o);
            if (lane >= o) x += t;
        }
        if (lane == 31) warpsum[wid] = x;
        __syncthreads();
        if (wid == 0) {
            int s = warpsum[lane];
#pragma unroll
            for (int o = 1; o < 32; o <<= 1) {
                int t = __shfl_up_sync(0xffffffffu, s, o);
                if (lane >= o) s += t;
            }
            warpsum[lane] = s;
        }
        __syncthreads();
        int pref  = (wid > 0) ? warpsum[wid - 1] : 0;
        int incl  = carry_s + pref + x;
        int excl  = incl - v;
        if (i < N) { g_rowptr[i] = excl; g_wpos[i] = excl; }
        __syncthreads();
        if (tid == 1023) carry_s = incl;
        __syncthreads();
    }
    if (threadIdx.x == 0) g_rowptr[N] = carry_s;
}

__global__ void scatter_k(const int* __restrict__ ei, int E, int N) {
    int i = blockIdx.x * blockDim.x + threadIdx.x;
    int Et = E + N;
    if (i >= Et) return;
    int src, dst;
    if (i < E) { src = ei[i]; dst = ei[E + i]; }
    else       { src = dst = i - E; }
    int pos = atomicAdd(&g_wpos[dst], 1);
    g_csrc[pos] = src;
}

// ---------------- fused softmax + aggregation + bias (+ELU / +pool), warp per dst ----------------
__global__ void __launch_bounds__(256)
aggr_k(const float* __restrict__ Hm,
       float* __restrict__ O,
       const float* __restrict__ bias,
       const int* __restrict__ batch,
       int N, int do_elu, int do_pool) {
    int d    = (blockIdx.x * blockDim.x + threadIdx.x) >> 5;
    int lane = threadIdx.x & 31;
    if (d >= N) return;
    int head = lane >> 3;

    float adh = g_ad[d * 4 + head];
    int i0 = g_rowptr[d];
    int i1 = g_rowptr[d + 1];

    float4 acc = make_float4(0.f, 0.f, 0.f, 0.f);
    float sw = 0.f;

    int s = (i0 < i1) ? __ldg(&g_csrc[i0]) : 0;
    for (int i = i0; i < i1; i++) {
        int s_cur = s;
        if (i + 1 < i1) s = __ldg(&g_csrc[i + 1]);
        float a = __ldg(&g_as[s_cur * 4 + head]);
        float4 hv = *(const float4*)&Hm[s_cur * F + lane * 4];
        float e = a + adh;
        e = e > 0.f ? e : 0.2f * e;
        float w = __expf(e);
        sw += w;
        acc.x = fmaf(w, hv.x, acc.x);
        acc.y = fmaf(w, hv.y, acc.y);
        acc.z = fmaf(w, hv.z, acc.z);
        acc.w = fmaf(w, hv.w, acc.w);
    }

    float inv = 1.0f / (sw + 1e-16f);
    float4 b4 = *(const float4*)&bias[lane * 4];
    float4 o;
    o.x = acc.x * inv + b4.x;
    o.y = acc.y * inv + b4.y;
    o.z = acc.z * inv + b4.z;
    o.w = acc.w * inv + b4.w;
    if (do_elu) {
        o.x = o.x > 0.f ? o.x : expm1f(o.x);
        o.y = o.y > 0.f ? o.y : expm1f(o.y);
        o.z = o.z > 0.f ? o.z : expm1f(o.z);
        o.w = o.w > 0.f ? o.w : expm1f(o.w);
    }

    if (do_pool) {
        int g = __ldg(&batch[d]);
        redAddV4(&g_psum[g * F + lane * 4], o.x, o.y, o.z, o.w);
        atomicMaxFloat(&g_pmax[g * F + lane * 4 + 0], o.x);
        atomicMaxFloat(&g_pmax[g * F + lane * 4 + 1], o.y);
        atomicMaxFloat(&g_pmax[g * F + lane * 4 + 2], o.z);
        atomicMaxFloat(&g_pmax[g * F + lane * 4 + 3], o.w);
        if (lane == 0) atomicAdd(&g_cnt[g], 1.0f);
    } else {
        *(float4*)&O[d * F + lane * 4] = o;
    }
}

// ---------------- pooling init + final ----------------
__global__ void pool_init_k() {
    int i = blockIdx.x * blockDim.x + threadIdx.x;
    if (i < GMAX * F) { g_psum[i] = 0.f; g_pmax[i] = -INFINITY; }
    if (i < GMAX) g_cnt[i] = 0.f;
}

__global__ void final_k(const float* __restrict__ lw, const float* __restrict__ lb,
                        float* __restrict__ out) {
    int g    = (blockIdx.x * blockDim.x + threadIdx.x) >> 5;
    int lane = threadIdx.x & 31;
    if (g >= GMAX) return;
    float cnt = fmaxf(g_cnt[g], 1.0f);
    float acc = 0.f;
#pragma unroll
    for (int j = 0; j < 4; j++) {
        int c = lane * 4 + j;
        float mean = g_psum[g * F + c] / cnt;
        float mx = g_pmax[g * F + c];
        if (isinf(mx)) mx = 0.f;
        acc += (mean + mx) * lw[c];
    }
#pragma unroll
    for (int o = 16; o; o >>= 1) acc += __shfl_down_sync(0xffffffffu, acc, o);
    if (lane == 0) out[g] = acc + lb[0];
}

// ---------------- launcher ----------------
extern "C" void kernel_launch(void* const* d_in, const int* in_sizes, int n_in,
                              void* d_out, int out_size) {
    const float* x     = (const float*)d_in[0];
    const int*   ei    = (const int*)d_in[1];
    const int*   batch = (const int*)d_in[2];
    const float* W1    = (const float*)d_in[3];
    const float* as1   = (const float*)d_in[4];
    const float* ad1   = (const float*)d_in[5];
    const float* b1    = (const float*)d_in[6];
    const float* W2    = (const float*)d_in[7];
    const float* as2   = (const float*)d_in[8];
    const float* ad2   = (const float*)d_in[9];
    const float* b2    = (const float*)d_in[10];
    const float* lw    = (const float*)d_in[11];
    const float* lb    = (const float*)d_in[12];

    int N  = in_sizes[0] / F;
    int E  = in_sizes[1] / 2;
    int Et = E + N;

    float *hptr, *bptr;
    cudaGetSymbolAddress((void**)&hptr, g_h);
    cudaGetSymbolAddress((void**)&bptr, g_buf);

    size_t smem = (size_t)(F * F + F * XPAD) * sizeof(float);
    cudaFuncSetAttribute(gemm_k, cudaFuncAttributeMaxDynamicSharedMemorySize, (int)smem);

    int gemm_blocks      = (N + 63) / 64;
    int node_warp_blocks = (N * 32 + 255) / 256;
    int edge_blocks      = (Et + 255) / 256;

    // ---- CSR build (topology shared by both layers) ----
    zero_deg_k<<<(N + 255) / 256, 256>>>(N);
    count_k<<<edge_blocks, 256>>>(ei, E, N);
    scan_k<<<1, 1024>>>(N);
    scatter_k<<<edge_blocks, 256>>>(ei, E, N);

    // ---- layer 1 (gemm + fused alpha, then fused softmax-aggregate+bias+ELU) ----
    gemm_k<<<gemm_blocks, 256, smem>>>(x, W1, hptr, as1, ad1, N);
    aggr_k<<<node_warp_blocks, 256>>>(hptr, bptr, b1, batch, N, 1, 0);

    // ---- layer 2 (pool fused into aggregation epilogue) ----
    pool_init_k<<<(GMAX * F + 255) / 256, 256>>>();
    gemm_k<<<gemm_blocks, 256, smem>>>(bptr, W2, hptr, as2, ad2, N);
    aggr_k<<<node_warp_blocks, 256>>>(hptr, bptr, b2, batch, N, 0, 1);

    // ---- final linear ----
    final_k<<<(GMAX * 32 + 255) / 256, 256>>>(lw, lb, (float*)d_out);
}

// round 6
// speedup vs baseline: 1.1637x; 1.0007x over previous
#include <cuda_runtime.h>
#include <math.h>

#define F      128
#define HEADS  4
#define NMAX   50000
#define GMAX   64
#define EMAX   860000
#define XPAD   68

// ---------------- device scratch ----------------
__device__ __align__(16) float g_h   [NMAX * F];
__device__ __align__(16) float g_buf [NMAX * F];
__device__ __align__(16) float g_as  [NMAX * HEADS];
__device__ __align__(16) float g_ad  [NMAX * HEADS];
__device__ __align__(16) float g_psum[GMAX * F];
__device__ __align__(16) float g_pmax[GMAX * F];
__device__             float g_cnt [GMAX];
__device__             int   g_deg [NMAX];
__device__             int   g_rowptr[NMAX + 1];
__device__             int   g_wpos[NMAX];
__device__             int   g_csrc[EMAX];

// ---------------- helpers ----------------
__device__ __forceinline__ void atomicMaxFloat(float* addr, float value) {
    if (value >= 0.f) atomicMax((int*)addr, __float_as_int(value));
    else              atomicMin((unsigned int*)addr, __float_as_uint(value));
}

__device__ __forceinline__ void redAddV4(float* p, float a, float b, float c, float d) {
    asm volatile("red.global.add.v4.f32 [%0], {%1,%2,%3,%4};"
                 :: "l"(p), "f"(a), "f"(b), "f"(c), "f"(d) : "memory");
}

// ---------------- GEMM + fused alpha: O = X @ W; g_as/g_ad per node ----------------
// W read directly from global (64KB, L1-resident). Only X tile in smem.
__global__ void gemm_k(const float* __restrict__ X, const float* __restrict__ W,
                       float* __restrict__ O,
                       const float* __restrict__ asr, const float* __restrict__ adt,
                       int N) {
    extern __shared__ float sm[];
    float* xs = sm;            // [128][XPAD]

    const int tid  = threadIdx.x;
    const int row0 = blockIdx.x * 64;

    const float4* X4 = (const float4*)X;
#pragma unroll
    for (int i = 0; i < 8; i++) {
        int idx = tid + i * 256;
        int r = idx >> 5, kq = idx & 31;
        float4 v = make_float4(0.f, 0.f, 0.f, 0.f);
        int gr = row0 + r;
        if (gr < N) v = X4[gr * 32 + kq];
        xs[(4 * kq + 0) * XPAD + r] = v.x;
        xs[(4 * kq + 1) * XPAD + r] = v.y;
        xs[(4 * kq + 2) * XPAD + r] = v.z;
        xs[(4 * kq + 3) * XPAD + r] = v.w;
    }
    __syncthreads();

    const int ty = tid >> 4, tx = tid & 15;
    float acc[4][8];
#pragma unroll
    for (int i = 0; i < 4; i++)
#pragma unroll
        for (int j = 0; j < 8; j++) acc[i][j] = 0.f;

#pragma unroll 4
    for (int k = 0; k < F; k++) {
        float4 x4 = *(const float4*)&xs[k * XPAD + ty * 4];
        float xr[4] = {x4.x, x4.y, x4.z, x4.w};
        float4 w0 = __ldg((const float4*)&W[k * F + tx * 8]);
        float4 w1 = __ldg((const float4*)&W[k * F + tx * 8 + 4]);
        float wr[8] = {w0.x, w0.y, w0.z, w0.w, w1.x, w1.y, w1.z, w1.w};
#pragma unroll
        for (int i = 0; i < 4; i++)
#pragma unroll
            for (int j = 0; j < 8; j++) acc[i][j] = fmaf(xr[i], wr[j], acc[i][j]);
    }

    // attention vectors for this thread's 8 columns (head = tx>>2)
    float4 a0 = *(const float4*)&asr[tx * 8];
    float4 a1 = *(const float4*)&asr[tx * 8 + 4];
    float4 d0 = *(const float4*)&adt[tx * 8];
    float4 d1 = *(const float4*)&adt[tx * 8 + 4];
    float av[8] = {a0.x, a0.y, a0.z, a0.w, a1.x, a1.y, a1.z, a1.w};
    float dv[8] = {d0.x, d0.y, d0.z, d0.w, d1.x, d1.y, d1.z, d1.w};

    const int lane = tid & 31;
    const int head = (lane >> 2) & 3;

#pragma unroll
    for (int i = 0; i < 4; i++) {
        int gr = row0 + ty * 4 + i;
        float ps = 0.f, pd = 0.f;
#pragma unroll
        for (int j = 0; j < 8; j++) {
            ps = fmaf(acc[i][j], av[j], ps);
            pd = fmaf(acc[i][j], dv[j], pd);
        }
        ps += __shfl_down_sync(0xffffffffu, ps, 1, 4);
        ps += __shfl_down_sync(0xffffffffu, ps, 2, 4);
        pd += __shfl_down_sync(0xffffffffu, pd, 1, 4);
        pd += __shfl_down_sync(0xffffffffu, pd, 2, 4);
        if (gr < N) {
            if ((lane & 3) == 0) {
                g_as[gr * 4 + head] = ps;
                g_ad[gr * 4 + head] = pd;
            }
            *(float4*)&O[gr * F + tx * 8]     = make_float4(acc[i][0], acc[i][1], acc[i][2], acc[i][3]);
            *(float4*)&O[gr * F + tx * 8 + 4] = make_float4(acc[i][4], acc[i][5], acc[i][6], acc[i][7]);
        }
    }
}

// ---------------- CSR build ----------------
__global__ void zero_deg_k(int N) {
    int i = blockIdx.x * blockDim.x + threadIdx.x;
    if (i < N) g_deg[i] = 0;
}

__global__ void count_k(const int* __restrict__ ei, int E, int N) {
    int i = blockIdx.x * blockDim.x + threadIdx.x;
    int Et = E + N;
    if (i >= Et) return;
    int dst = (i < E) ? ei[E + i] : (i - E);
    atomicAdd(&g_deg[dst], 1);
}

// single-block exclusive scan (warp-shuffle based)
__global__ void scan_k(int N) {
    __shared__ int warpsum[32];
    __shared__ int carry_s;
    int tid = threadIdx.x, lane = tid & 31, wid = tid >> 5;
    if (tid == 0) carry_s = 0;
    __syncthreads();
    for (int base = 0; base < N; base += 1024) {
        int i = base + tid;
        int v = (i < N) ? g_deg[i] : 0;
        int x = v;
#pragma unroll
        for (int o = 1; o < 32; o <<= 1) {
            int t = __shfl_up_sync(0xffffffffu, x, o);
            if (lane >= o) x += t;
        }
        if (lane == 31) warpsum[wid] = x;
        __syncthreads();
        if (wid == 0) {
            int s = warpsum[lane];
#pragma unroll
            for (int o = 1; o < 32; o <<= 1) {
                int t = __shfl_up_sync(0xffffffffu, s, o);
                if (lane >= o) s += t;
            }
            warpsum[lane] = s;
        }
        __syncthreads();
        int pref  = (wid > 0) ? warpsum[wid - 1] : 0;
        int incl  = carry_s + pref + x;
        int excl  = incl - v;
        if (i < N) { g_rowptr[i] = excl; g_wpos[i] = excl; }
        __syncthreads();
        if (tid == 1023) carry_s = incl;
        __syncthreads();
    }
    if (threadIdx.x == 0) g_rowptr[N] = carry_s;
}

__global__ void scatter_k(const int* __restrict__ ei, int E, int N) {
    int i = blockIdx.x * blockDim.x + threadIdx.x;
    int Et = E + N;
    if (i >= Et) return;
    int src, dst;
    if (i < E) { src = ei[i]; dst = ei[E + i]; }
    else       { src = dst = i - E; }
    int pos = atomicAdd(&g_wpos[dst], 1);
    g_csrc[pos] = src;
}

// ---------------- fused softmax + aggregation + bias (+ELU / +pool), warp per dst ----------------
// Depth-1 software pipeline: edge i+1's (a, hv) loads issue before edge i's compute.
__global__ void __launch_bounds__(256)
aggr_k(const float* __restrict__ Hm,
       float* __restrict__ O,
       const float* __restrict__ bias,
       const int* __restrict__ batch,
       int N, int do_elu, int do_pool) {
    int d    = (blockIdx.x * blockDim.x + threadIdx.x) >> 5;
    int lane = threadIdx.x & 31;
    if (d >= N) return;
    int head = lane >> 3;

    float adh = g_ad[d * 4 + head];
    int i0 = g_rowptr[d];
    int i1 = g_rowptr[d + 1];

    float4 acc = make_float4(0.f, 0.f, 0.f, 0.f);
    float sw = 0.f;

    float  a_next  = 0.f;
    float4 hv_next = make_float4(0.f, 0.f, 0.f, 0.f);
    if (i0 < i1) {
        int sn = __ldg(&g_csrc[i0]);
        a_next  = __ldg(&g_as[sn * 4 + head]);
        hv_next = *(const float4*)&Hm[sn * F + lane * 4];
    }

    for (int i = i0; i < i1; i++) {
        float  a  = a_next;
        float4 hv = hv_next;
        if (i + 1 < i1) {
            int sn = __ldg(&g_csrc[i + 1]);
            a_next  = __ldg(&g_as[sn * 4 + head]);
            hv_next = *(const float4*)&Hm[sn * F + lane * 4];
        }
        float e = a + adh;
        e = e > 0.f ? e : 0.2f * e;
        float w = __expf(e);
        sw += w;
        acc.x = fmaf(w, hv.x, acc.x);
        acc.y = fmaf(w, hv.y, acc.y);
        acc.z = fmaf(w, hv.z, acc.z);
        acc.w = fmaf(w, hv.w, acc.w);
    }

    float inv = 1.0f / (sw + 1e-16f);
    float4 b4 = *(const float4*)&bias[lane * 4];
    float4 o;
    o.x = acc.x * inv + b4.x;
    o.y = acc.y * inv + b4.y;
    o.z = acc.z * inv + b4.z;
    o.w = acc.w * inv + b4.w;
    if (do_elu) {
        o.x = o.x > 0.f ? o.x : expm1f(o.x);
        o.y = o.y > 0.f ? o.y : expm1f(o.y);
        o.z = o.z > 0.f ? o.z : expm1f(o.z);
        o.w = o.w > 0.f ? o.w : expm1f(o.w);
    }

    if (do_pool) {
        int g = __ldg(&batch[d]);
        redAddV4(&g_psum[g * F + lane * 4], o.x, o.y, o.z, o.w);
        atomicMaxFloat(&g_pmax[g * F + lane * 4 + 0], o.x);
        atomicMaxFloat(&g_pmax[g * F + lane * 4 + 1], o.y);
        atomicMaxFloat(&g_pmax[g * F + lane * 4 + 2], o.z);
        atomicMaxFloat(&g_pmax[g * F + lane * 4 + 3], o.w);
        if (lane == 0) atomicAdd(&g_cnt[g], 1.0f);
    } else {
        *(float4*)&O[d * F + lane * 4] = o;
    }
}

// ---------------- pooling init + final ----------------
__global__ void pool_init_k() {
    int i = blockIdx.x * blockDim.x + threadIdx.x;
    if (i < GMAX * F) { g_psum[i] = 0.f; g_pmax[i] = -INFINITY; }
    if (i < GMAX) g_cnt[i] = 0.f;
}

__global__ void final_k(const float* __restrict__ lw, const float* __restrict__ lb,
                        float* __restrict__ out) {
    int g    = (blockIdx.x * blockDim.x + threadIdx.x) >> 5;
    int lane = threadIdx.x & 31;
    if (g >= GMAX) return;
    float cnt = fmaxf(g_cnt[g], 1.0f);
    float acc = 0.f;
#pragma unroll
    for (int j = 0; j < 4; j++) {
        int c = lane * 4 + j;
        float mean = g_psum[g * F + c] / cnt;
        float mx = g_pmax[g * F + c];
        if (isinf(mx)) mx = 0.f;
        acc += (mean + mx) * lw[c];
    }
#pragma unroll
    for (int o = 16; o; o >>= 1) acc += __shfl_down_sync(0xffffffffu, acc, o);
    if (lane == 0) out[g] = acc + lb[0];
}

// ---------------- launcher ----------------
extern "C" void kernel_launch(void* const* d_in, const int* in_sizes, int n_in,
                              void* d_out, int out_size) {
    const float* x     = (const float*)d_in[0];
    const int*   ei    = (const int*)d_in[1];
    const int*   batch = (const int*)d_in[2];
    const float* W1    = (const float*)d_in[3];
    const float* as1   = (const float*)d_in[4];
    const float* ad1   = (const float*)d_in[5];
    const float* b1    = (const float*)d_in[6];
    const float* W2    = (const float*)d_in[7];
    const float* as2   = (const float*)d_in[8];
    const float* ad2   = (const float*)d_in[9];
    const float* b2    = (const float*)d_in[10];
    const float* lw    = (const float*)d_in[11];
    const float* lb    = (const float*)d_in[12];

    int N  = in_sizes[0] / F;
    int E  = in_sizes[1] / 2;
    int Et = E + N;

    float *hptr, *bptr;
    cudaGetSymbolAddress((void**)&hptr, g_h);
    cudaGetSymbolAddress((void**)&bptr, g_buf);

    size_t smem = (size_t)(F * XPAD) * sizeof(float);
    cudaFuncSetAttribute(gemm_k, cudaFuncAttributeMaxDynamicSharedMemorySize, (int)smem);

    int gemm_blocks      = (N + 63) / 64;
    int node_warp_blocks = (N * 32 + 255) / 256;
    int edge_blocks      = (Et + 255) / 256;

    // ---- CSR build (topology shared by both layers) ----
    zero_deg_k<<<(N + 255) / 256, 256>>>(N);
    count_k<<<edge_blocks, 256>>>(ei, E, N);
    scan_k<<<1, 1024>>>(N);
    scatter_k<<<edge_blocks, 256>>>(ei, E, N);

    // ---- layer 1 (gemm + fused alpha, then fused softmax-aggregate+bias+ELU) ----
    gemm_k<<<gemm_blocks, 256, smem>>>(x, W1, hptr, as1, ad1, N);
    aggr_k<<<node_warp_blocks, 256>>>(hptr, bptr, b1, batch, N, 1, 0);

    // ---- layer 2 (pool fused into aggregation epilogue) ----
    pool_init_k<<<(GMAX * F + 255) / 256, 256>>>();
    gemm_k<<<gemm_blocks, 256, smem>>>(bptr, W2, hptr, as2, ad2, N);
    aggr_k<<<node_warp_blocks, 256>>>(hptr, bptr, b2, batch, N, 0, 1);

    // ---- final linear ----
    final_k<<<(GMAX * 32 + 255) / 256, 256>>>(lw, lb, (float*)d_out);
}